// round 9
// baseline (speedup 1.0000x reference)
#include <cuda_runtime.h>
#include <cuda_fp16.h>
#include <math.h>
#include <stdint.h>

#define EMBED   1024
#define BATCH   2
#define SEQ     2048
#define NHEADS  8
#define HDIM    64
#define DVDIM   128
#define H2      16
#define LAMBDA_INIT 0.8f

// -------- scratch (static device arrays: allocation-free rule) --------
__device__ __half g_Qp[BATCH*SEQ*EMBED];
__device__ __half g_Kp[BATCH*SEQ*EMBED];
__device__ __half g_Vp[BATCH*SEQ*EMBED];
__device__ __half g_Xh[BATCH*SEQ*EMBED];   // fused flash output (fp16)
__device__ float  g_lambda;

// ---------------- helpers ----------------
__device__ __forceinline__ uint32_t smem_u32(const void* p) {
    uint32_t a;
    asm("{ .reg .u64 t; cvta.to.shared.u64 t, %1; cvt.u32.u64 %0, t; }"
        : "=r"(a) : "l"(p));
    return a;
}

__device__ __forceinline__ unsigned f2h2(float x, float y) {
    __half2 h = __floats2half2_rn(x, y);
    return *(unsigned*)&h;
}

__device__ __forceinline__ float ex2f(float x) {
    float y;
    asm("ex2.approx.f32 %0, %1;" : "=f"(y) : "f"(x));
    return y;
}

__device__ __forceinline__ unsigned e2pack(float x, float y) {
    unsigned h;
    float ex = ex2f(x), ey = ex2f(y);
    asm("cvt.rn.f16x2.f32 %0, %2, %1;" : "=r"(h) : "f"(ex), "f"(ey));
    return h;
}

__device__ __forceinline__ void mma16(float c[4], const unsigned a[4], const unsigned b[2]) {
    asm volatile(
        "mma.sync.aligned.m16n8k16.row.col.f32.f16.f16.f32 "
        "{%0,%1,%2,%3},{%4,%5,%6,%7},{%8,%9},{%0,%1,%2,%3};"
        : "+f"(c[0]), "+f"(c[1]), "+f"(c[2]), "+f"(c[3])
        : "r"(a[0]), "r"(a[1]), "r"(a[2]), "r"(a[3]), "r"(b[0]), "r"(b[1]));
}

__device__ __forceinline__ void ldsm4(uint32_t a, unsigned& r0, unsigned& r1,
                                      unsigned& r2, unsigned& r3) {
    asm volatile("ldmatrix.sync.aligned.m8n8.x4.shared.b16 {%0,%1,%2,%3}, [%4];"
                 : "=r"(r0), "=r"(r1), "=r"(r2), "=r"(r3) : "r"(a));
}

__device__ __forceinline__ void ldsm4t(uint32_t a, unsigned& r0, unsigned& r1,
                                       unsigned& r2, unsigned& r3) {
    asm volatile("ldmatrix.sync.aligned.m8n8.x4.trans.shared.b16 {%0,%1,%2,%3}, [%4];"
                 : "=r"(r0), "=r"(r1), "=r"(r2), "=r"(r3) : "r"(a));
}

#define CP16(dst, src) \
    asm volatile("cp.async.cg.shared.global [%0], [%1], 16;" :: "r"(dst), "l"(src))
#define CP_COMMIT() asm volatile("cp.async.commit_group;" ::: "memory")
#define CP_WAIT(n)  asm volatile("cp.async.wait_group %0;" :: "n"(n) : "memory")

// ======================================================================
// fp16 GEMM (A fp32): C[M,N] = alpha * A[M,K] @ W[N,K]^T  -> fp16 C
// ======================================================================
#define GSTR 40
#define GBUF (128*GSTR)
__global__ void __launch_bounds__(256) gemm_fp16(
    const float* __restrict__ A, const float* __restrict__ W,
    __half* __restrict__ C, int M, int N, int K, float alpha)
{
    __shared__ __half As[2][GBUF];
    __shared__ __half Ws[2][GBUF];

    const int tid = threadIdx.x, lane = tid & 31, warp = tid >> 5;
    const int wm = warp >> 2, wn = warp & 3;
    const int m0 = blockIdx.y << 7, n0 = blockIdx.x << 7;
    const int g = lane >> 2, q = lane & 3;
    const int lm = lane >> 3, lr = lane & 7;

    const int lrow = tid >> 1;
    const int lk   = (tid & 1) << 4;
    const float* Ag = A + (size_t)(m0 + lrow) * K + lk;
    const float* Wg = W + (size_t)(n0 + lrow) * K + lk;

    float acc[4][4][4] = {};

    const uint32_t aB = smem_u32(As), wB = smem_u32(Ws);
    const int arow = (wm << 6) + ((lm & 1) << 3) + lr;
    const int acol = (lm >> 1) << 3;
    const int brow = (wn << 5) + ((lm >> 1) << 3) + lr;
    const int bcol = (lm & 1) << 3;

    float4 fa[4], fw[4];
#pragma unroll
    for (int i = 0; i < 4; ++i) {
        fa[i] = *(const float4*)(Ag + (i << 2));
        fw[i] = *(const float4*)(Wg + (i << 2));
    }
#pragma unroll
    for (int h = 0; h < 2; ++h) {
        uint4 ua = make_uint4(f2h2(fa[2*h].x, fa[2*h].y),  f2h2(fa[2*h].z, fa[2*h].w),
                              f2h2(fa[2*h+1].x, fa[2*h+1].y), f2h2(fa[2*h+1].z, fa[2*h+1].w));
        uint4 uw = make_uint4(f2h2(fw[2*h].x, fw[2*h].y),  f2h2(fw[2*h].z, fw[2*h].w),
                              f2h2(fw[2*h+1].x, fw[2*h+1].y), f2h2(fw[2*h+1].z, fw[2*h+1].w));
        *(uint4*)&As[0][lrow*GSTR + lk + 8*h] = ua;
        *(uint4*)&Ws[0][lrow*GSTR + lk + 8*h] = uw;
    }
    __syncthreads();

    const int NK = K >> 5;
    for (int kt = 0; kt < NK; ++kt) {
        if (kt + 1 < NK) {
            const int kc = (kt + 1) << 5;
#pragma unroll
            for (int i = 0; i < 4; ++i) {
                fa[i] = *(const float4*)(Ag + kc + (i << 2));
                fw[i] = *(const float4*)(Wg + kc + (i << 2));
            }
        }
        const int buf = kt & 1;
        const uint32_t aBb = aB + buf * (GBUF * 2);
        const uint32_t wBb = wB + buf * (GBUF * 2);
#pragma unroll
        for (int ks = 0; ks < 2; ++ks) {
            unsigned af[4][4], bf[4][2];
#pragma unroll
            for (int mi = 0; mi < 4; ++mi)
                ldsm4(aBb + ((arow + (mi << 4)) * GSTR + (ks << 4) + acol) * 2,
                      af[mi][0], af[mi][1], af[mi][2], af[mi][3]);
#pragma unroll
            for (int np = 0; np < 2; ++np) {
                unsigned r0, r1, r2, r3;
                ldsm4(wBb + ((brow + (np << 4)) * GSTR + (ks << 4) + bcol) * 2,
                      r0, r1, r2, r3);
                bf[2*np][0] = r0; bf[2*np][1] = r1;
                bf[2*np+1][0] = r2; bf[2*np+1][1] = r3;
            }
#pragma unroll
            for (int mi = 0; mi < 4; ++mi)
#pragma unroll
                for (int ni = 0; ni < 4; ++ni)
                    mma16(acc[mi][ni], af[mi], bf[ni]);
        }
        __syncthreads();
        if (kt + 1 < NK) {
            const int nb = (kt + 1) & 1;
#pragma unroll
            for (int h = 0; h < 2; ++h) {
                uint4 ua = make_uint4(f2h2(fa[2*h].x, fa[2*h].y),  f2h2(fa[2*h].z, fa[2*h].w),
                                      f2h2(fa[2*h+1].x, fa[2*h+1].y), f2h2(fa[2*h+1].z, fa[2*h+1].w));
                uint4 uw = make_uint4(f2h2(fw[2*h].x, fw[2*h].y),  f2h2(fw[2*h].z, fw[2*h].w),
                                      f2h2(fw[2*h+1].x, fw[2*h+1].y), f2h2(fw[2*h+1].z, fw[2*h+1].w));
                *(uint4*)&As[nb][lrow*GSTR + lk + 8*h] = ua;
                *(uint4*)&Ws[nb][lrow*GSTR + lk + 8*h] = uw;
            }
            __syncthreads();
        }
    }

#pragma unroll
    for (int mi = 0; mi < 4; ++mi)
#pragma unroll
        for (int ni = 0; ni < 4; ++ni) {
            const int r0 = m0 + (wm << 6) + (mi << 4) + g;
            const int cc = n0 + (wn << 5) + (ni << 3) + 2 * q;
            *(unsigned*)&C[(size_t)r0 * N + cc] =
                f2h2(acc[mi][ni][0] * alpha, acc[mi][ni][1] * alpha);
            *(unsigned*)&C[(size_t)(r0 + 8) * N + cc] =
                f2h2(acc[mi][ni][2] * alpha, acc[mi][ni][3] * alpha);
        }
}

// ======================================================================
// fp16 GEMM (A fp16): C fp32 = A[M,K](half) @ W[N,K]^T(fp32)
// FIXED: A loader now moves all 16 halves (two uint4), not 8.
// ======================================================================
__global__ void __launch_bounds__(256) gemm_h16(
    const __half* __restrict__ A, const float* __restrict__ W,
    float* __restrict__ C, int M, int N, int K, float alpha)
{
    __shared__ __half As[2][GBUF];
    __shared__ __half Ws[2][GBUF];

    const int tid = threadIdx.x, lane = tid & 31, warp = tid >> 5;
    const int wm = warp >> 2, wn = warp & 3;
    const int m0 = blockIdx.y << 7, n0 = blockIdx.x << 7;
    const int g = lane >> 2, q = lane & 3;
    const int lm = lane >> 3, lr = lane & 7;

    const int lrow = tid >> 1;
    const int lk   = (tid & 1) << 4;
    const __half* Ag = A + (size_t)(m0 + lrow) * K + lk;
    const float*  Wg = W + (size_t)(n0 + lrow) * K + lk;

    float acc[4][4][4] = {};

    const uint32_t aB = smem_u32(As), wB = smem_u32(Ws);
    const int arow = (wm << 6) + ((lm & 1) << 3) + lr;
    const int acol = (lm >> 1) << 3;
    const int brow = (wn << 5) + ((lm >> 1) << 3) + lr;
    const int bcol = (lm & 1) << 3;

    uint4 ha0, ha1;
    float4 fw[4];
    ha0 = *(const uint4*)Ag;
    ha1 = *(const uint4*)(Ag + 8);
#pragma unroll
    for (int i = 0; i < 4; ++i) fw[i] = *(const float4*)(Wg + (i << 2));
    *(uint4*)&As[0][lrow*GSTR + lk]     = ha0;
    *(uint4*)&As[0][lrow*GSTR + lk + 8] = ha1;
#pragma unroll
    for (int h = 0; h < 2; ++h) {
        uint4 uw = make_uint4(f2h2(fw[2*h].x, fw[2*h].y),  f2h2(fw[2*h].z, fw[2*h].w),
                              f2h2(fw[2*h+1].x, fw[2*h+1].y), f2h2(fw[2*h+1].z, fw[2*h+1].w));
        *(uint4*)&Ws[0][lrow*GSTR + lk + 8*h] = uw;
    }
    __syncthreads();

    const int NK = K >> 5;
    for (int kt = 0; kt < NK; ++kt) {
        if (kt + 1 < NK) {
            const int kc = (kt + 1) << 5;
            ha0 = *(const uint4*)(Ag + kc);
            ha1 = *(const uint4*)(Ag + kc + 8);
#pragma unroll
            for (int i = 0; i < 4; ++i) fw[i] = *(const float4*)(Wg + kc + (i << 2));
        }
        const int buf = kt & 1;
        const uint32_t aBb = aB + buf * (GBUF * 2);
        const uint32_t wBb = wB + buf * (GBUF * 2);
#pragma unroll
        for (int ks = 0; ks < 2; ++ks) {
            unsigned af[4][4], bf[4][2];
#pragma unroll
            for (int mi = 0; mi < 4; ++mi)
                ldsm4(aBb + ((arow + (mi << 4)) * GSTR + (ks << 4) + acol) * 2,
                      af[mi][0], af[mi][1], af[mi][2], af[mi][3]);
#pragma unroll
            for (int np = 0; np < 2; ++np) {
                unsigned r0, r1, r2, r3;
                ldsm4(wBb + ((brow + (np << 4)) * GSTR + (ks << 4) + bcol) * 2,
                      r0, r1, r2, r3);
                bf[2*np][0] = r0; bf[2*np][1] = r1;
                bf[2*np+1][0] = r2; bf[2*np+1][1] = r3;
            }
#pragma unroll
            for (int mi = 0; mi < 4; ++mi)
#pragma unroll
                for (int ni = 0; ni < 4; ++ni)
                    mma16(acc[mi][ni], af[mi], bf[ni]);
        }
        __syncthreads();
        if (kt + 1 < NK) {
            const int nb = (kt + 1) & 1;
            *(uint4*)&As[nb][lrow*GSTR + lk]     = ha0;
            *(uint4*)&As[nb][lrow*GSTR + lk + 8] = ha1;
#pragma unroll
            for (int h = 0; h < 2; ++h) {
                uint4 uw = make_uint4(f2h2(fw[2*h].x, fw[2*h].y),  f2h2(fw[2*h].z, fw[2*h].w),
                                      f2h2(fw[2*h+1].x, fw[2*h+1].y), f2h2(fw[2*h+1].z, fw[2*h+1].w));
                *(uint4*)&Ws[nb][lrow*GSTR + lk + 8*h] = uw;
            }
            __syncthreads();
        }
    }

#pragma unroll
    for (int mi = 0; mi < 4; ++mi)
#pragma unroll
        for (int ni = 0; ni < 4; ++ni) {
            const int r0 = m0 + (wm << 6) + (mi << 4) + g;
            const int cc = n0 + (wn << 5) + (ni << 3) + 2 * q;
            *(float2*)&C[(size_t)r0 * N + cc] =
                make_float2(acc[mi][ni][0] * alpha, acc[mi][ni][1] * alpha);
            *(float2*)&C[(size_t)(r0 + 8) * N + cc] =
                make_float2(acc[mi][ni][2] * alpha, acc[mi][ni][3] * alpha);
        }
}

// ======================================================================
// lambda_full
// ======================================================================
__global__ void lambda_kernel(const float* __restrict__ lq1, const float* __restrict__ lk1,
                              const float* __restrict__ lq2, const float* __restrict__ lk2)
{
    const int t = threadIdx.x;   // 64 threads
    float s1 = lq1[t] * lk1[t];
    float s2 = lq2[t] * lk2[t];
#pragma unroll
    for (int off = 16; off > 0; off >>= 1) {
        s1 += __shfl_xor_sync(0xffffffffu, s1, off);
        s2 += __shfl_xor_sync(0xffffffffu, s2, off);
    }
    __shared__ float w1[2], w2[2];
    if ((t & 31) == 0) { w1[t >> 5] = s1; w2[t >> 5] = s2; }
    __syncthreads();
    if (t == 0)
        g_lambda = expf(w1[0] + w1[1]) - expf(w2[0] + w2[1]) + LAMBDA_INIT;
}

// ======================================================================
// Fused flash attention for a HEAD PAIR (2hv, 2hv+1) + diff + RMSNorm.
// 512 threads = 16 warps: (rg 0..3) x (ch 0..1) x (head 0..1).
// ======================================================================
#define FTILE (64*136)
__global__ void __launch_bounds__(512, 1) flash_fused(
    const __half* __restrict__ Qp, const __half* __restrict__ Kp,
    const __half* __restrict__ Vp, __half* __restrict__ Xh)
{
    extern __shared__ __half fsm[];
    __half* Qs = fsm;                 // [64][136] both heads
    __half* Ks = fsm + FTILE;         // 2 buffers
    __half* Vs = fsm + 3*FTILE;       // 2 buffers

    const int tid = threadIdx.x, lane = tid & 31, wid = tid >> 5;
    const int g = lane >> 2, q = lane & 3;
    const int lm = lane >> 3, lr = lane & 7;
    const int head = wid & 1, ch = (wid >> 1) & 1, rg = wid >> 2;
    const int qt = blockIdx.x, bhv = blockIdx.y;
    const int b = bhv >> 3, hv = bhv & 7;
    const int t0 = qt << 6;
    const int mrow = rg << 4;

    const __half* qg = Qp + (size_t)b*SEQ*EMBED + hv*DVDIM;
    const __half* kg = Kp + (size_t)b*SEQ*EMBED + hv*DVDIM;
    const __half* vg = Vp + (size_t)b*SEQ*EMBED + hv*DVDIM;

    const uint32_t qB = smem_u32(Qs), kB = smem_u32(Ks), vB = smem_u32(Vs);

    // ---- Q tile: 64 rows x 128 halves ----
#pragma unroll
    for (int it = 0; it < 2; ++it) {
        const int c = tid + (it << 9);
        const int row = c >> 4, off = (c & 15) << 3;
        *(uint4*)&Qs[row*136 + off] =
            *(const uint4*)&qg[(size_t)(t0 + row) * EMBED + off];
    }

    // ---- preload K/V tile 0 ----
#pragma unroll
    for (int it = 0; it < 2; ++it) {
        const int c = tid + (it << 9);
        const int row = c >> 4, off = (c & 15) << 3;
        CP16(kB + (row*136 + off) * 2, kg + (size_t)row * EMBED + off);
        CP16(vB + (row*136 + off) * 2, vg + (size_t)row * EMBED + off);
    }
    CP_COMMIT();
    __syncthreads();

    // ---- Q fragments (this warp's head) ----
    unsigned qa[4][4];
    {
        const int qrow = mrow + ((lm & 1) << 3) + lr;
        const int qcol = (head << 6) + ((lm >> 1) << 3);
#pragma unroll
        for (int ks = 0; ks < 4; ++ks)
            ldsm4(qB + (qrow*136 + (ks << 4) + qcol) * 2,
                  qa[ks][0], qa[ks][1], qa[ks][2], qa[ks][3]);
    }

    float o[8][4];
#pragma unroll
    for (int i = 0; i < 8; ++i)
#pragma unroll
        for (int r = 0; r < 4; ++r) o[i][r] = 0.f;
    float lacc[4] = {0.f, 0.f, 0.f, 0.f};
    const unsigned ones[2] = {0x3C003C00u, 0x3C003C00u};

    const int kfrow = ((lm >> 1) << 3) + lr;
    const int kcsel = (head << 6) + ((lm & 1) << 3);
    const int vfrow = ((lm & 1) << 3) + lr;
    const int vcsel = lm >> 1;

    const int NT = SEQ / 64;
    for (int ti = 0; ti < NT; ++ti) {
        const int buf = ti & 1;
        if (ti + 1 < NT) {
            const int s1r = (ti + 1) << 6;
            const uint32_t kD = kB + (buf ^ 1) * FTILE * 2;
            const uint32_t vD = vB + (buf ^ 1) * FTILE * 2;
#pragma unroll
            for (int it = 0; it < 2; ++it) {
                const int c = tid + (it << 9);
                const int row = c >> 4, off = (c & 15) << 3;
                CP16(kD + (row*136 + off) * 2, kg + (size_t)(s1r + row) * EMBED + off);
                CP16(vD + (row*136 + off) * 2, vg + (size_t)(s1r + row) * EMBED + off);
            }
            CP_COMMIT();
            CP_WAIT(1);
        } else {
            CP_WAIT(0);
        }
        __syncthreads();

        const uint32_t kBb = kB + buf * FTILE * 2;
        const uint32_t vBb = vB + buf * FTILE * 2;

        // ---- S = Q @ K^T (this head) ----
        float s[8][4];
#pragma unroll
        for (int nt = 0; nt < 8; ++nt)
#pragma unroll
            for (int r = 0; r < 4; ++r) s[nt][r] = 0.f;
#pragma unroll
        for (int ks = 0; ks < 4; ++ks) {
            unsigned kb[8][2];
#pragma unroll
            for (int np = 0; np < 4; ++np) {
                unsigned r0, r1, r2, r3;
                ldsm4(kBb + (((np << 4) + kfrow)*136 + (ks << 4) + kcsel) * 2,
                      r0, r1, r2, r3);
                kb[2*np][0] = r0; kb[2*np][1] = r1;
                kb[2*np+1][0] = r2; kb[2*np+1][1] = r3;
            }
#pragma unroll
            for (int nt = 0; nt < 8; ++nt)
                mma16(s[nt], qa[ks], kb[nt]);
        }

        // ---- P = exp2(S), packed as PV A-fragments ----
        unsigned pa[4][4];
#pragma unroll
        for (int t = 0; t < 4; ++t) {
            pa[t][0] = e2pack(s[2*t][0],   s[2*t][1]);
            pa[t][1] = e2pack(s[2*t][2],   s[2*t][3]);
            pa[t][2] = e2pack(s[2*t+1][0], s[2*t+1][1]);
            pa[t][3] = e2pack(s[2*t+1][2], s[2*t+1][3]);
        }

        // ---- l += P @ ones ----
#pragma unroll
        for (int t = 0; t < 4; ++t)
            mma16(lacc, pa[t], ones);

        // ---- O += P @ V (this warp's 64-col half; V shared by heads) ----
#pragma unroll
        for (int ks = 0; ks < 4; ++ks) {
#pragma unroll
            for (int cp = 0; cp < 4; ++cp) {
                unsigned r0, r1, r2, r3;
                const int colt = (ch << 3) + (cp << 1);
                ldsm4t(vBb + (((ks << 4) + vfrow)*136 + (colt + vcsel)*8) * 2,
                       r0, r1, r2, r3);
                unsigned vb0[2] = {r0, r1}, vb1[2] = {r2, r3};
                mma16(o[2*cp],   pa[ks], vb0);
                mma16(o[2*cp+1], pa[ks], vb1);
            }
        }
        __syncthreads();
    }

    // ================= fused epilogue =================
    float* Zs = (float*)fsm;               // [64][130]
    float* Rs = (float*)fsm + 64*130;      // [2][64]
    const float lam = g_lambda;
    const float inv0 = 1.f / lacc[0], inv1 = 1.f / lacc[2];
    const int row0 = mrow + g, row1 = mrow + 8 + g;

    __syncthreads();   // done with smem tiles
    if (head == 1) {   // stage normalized O1
#pragma unroll
        for (int ct = 0; ct < 8; ++ct) {
            const int col = (ch << 6) + (ct << 3) + 2 * q;
            Zs[row0*130 + col]     = o[ct][0] * inv0;
            Zs[row0*130 + col + 1] = o[ct][1] * inv0;
            Zs[row1*130 + col]     = o[ct][2] * inv1;
            Zs[row1*130 + col + 1] = o[ct][3] * inv1;
        }
    }
    __syncthreads();

    float y[8][4];
    if (head == 0) {
        float p0 = 0.f, p1 = 0.f;
#pragma unroll
        for (int ct = 0; ct < 8; ++ct) {
            const int col = (ch << 6) + (ct << 3) + 2 * q;
            y[ct][0] = o[ct][0] * inv0 - lam * Zs[row0*130 + col];
            y[ct][1] = o[ct][1] * inv0 - lam * Zs[row0*130 + col + 1];
            y[ct][2] = o[ct][2] * inv1 - lam * Zs[row1*130 + col];
            y[ct][3] = o[ct][3] * inv1 - lam * Zs[row1*130 + col + 1];
            p0 += y[ct][0]*y[ct][0] + y[ct][1]*y[ct][1];
            p1 += y[ct][2]*y[ct][2] + y[ct][3]*y[ct][3];
        }
        p0 += __shfl_xor_sync(0xffffffffu, p0, 1);
        p0 += __shfl_xor_sync(0xffffffffu, p0, 2);
        p1 += __shfl_xor_sync(0xffffffffu, p1, 1);
        p1 += __shfl_xor_sync(0xffffffffu, p1, 2);
        if (q == 0) {
            Rs[ch*64 + row0] = p0;
            Rs[ch*64 + row1] = p1;
        }
    }
    __syncthreads();

    if (head == 0) {
        const float sc = 1.f - LAMBDA_INIT;
        const float r0s = rsqrtf((Rs[row0] + Rs[64 + row0]) * (1.f/128.f) + 1e-5f) * sc;
        const float r1s = rsqrtf((Rs[row1] + Rs[64 + row1]) * (1.f/128.f) + 1e-5f) * sc;
        __half* xb = Xh + ((size_t)b*SEQ + t0) * EMBED + hv*DVDIM + (ch << 6);
#pragma unroll
        for (int ct = 0; ct < 8; ++ct) {
            const int col = (ct << 3) + 2 * q;
            *(unsigned*)&xb[(size_t)row0 * EMBED + col] = f2h2(y[ct][0]*r0s, y[ct][1]*r0s);
            *(unsigned*)&xb[(size_t)row1 * EMBED + col] = f2h2(y[ct][2]*r1s, y[ct][3]*r1s);
        }
    }
}

// ======================================================================
extern "C" void kernel_launch(void* const* d_in, const int* in_sizes, int n_in,
                              void* d_out, int out_size)
{
    const float* q   = (const float*)d_in[0];
    const float* k   = (const float*)d_in[1];
    const float* v   = (const float*)d_in[2];
    const float* Wq  = (const float*)d_in[3];
    const float* Wk  = (const float*)d_in[4];
    const float* Wv  = (const float*)d_in[5];
    const float* Wo  = (const float*)d_in[6];
    const float* lq1 = (const float*)d_in[7];
    const float* lk1 = (const float*)d_in[8];
    const float* lq2 = (const float*)d_in[9];
    const float* lk2 = (const float*)d_in[10];
    float* out = (float*)d_out;

    __half *Qp, *Kp, *Vp, *Xh;
    cudaGetSymbolAddress((void**)&Qp, g_Qp);
    cudaGetSymbolAddress((void**)&Kp, g_Kp);
    cudaGetSymbolAddress((void**)&Vp, g_Vp);
    cudaGetSymbolAddress((void**)&Xh, g_Xh);

    const int SMEM_FLASH = 5 * FTILE * (int)sizeof(__half);   // 87040
    cudaFuncSetAttribute(flash_fused,
                         cudaFuncAttributeMaxDynamicSharedMemorySize, SMEM_FLASH);

    const int M = BATCH * SEQ;          // 4096
    dim3 gproj(EMBED/128, M/128);       // (8, 32)

    const float qscale = 0.125f * 1.4426950408889634f;  // d^-0.5 * log2(e)

    // lambda first so ncu's 4th-launch capture lands on gemm_fp16 (V proj)
    lambda_kernel<<<1, 64>>>(lq1, lk1, lq2, lk2);
    gemm_fp16<<<gproj, 256>>>(q, Wq, Qp, M, EMBED, EMBED, qscale);
    gemm_fp16<<<gproj, 256>>>(k, Wk, Kp, M, EMBED, EMBED, 1.0f);
    gemm_fp16<<<gproj, 256>>>(v, Wv, Vp, M, EMBED, EMBED, 1.0f);
    flash_fused<<<dim3(SEQ/64, BATCH*NHEADS), 512, SMEM_FLASH>>>(Qp, Kp, Vp, Xh);
    gemm_h16<<<gproj, 256>>>(Xh, Wo, out, M, EMBED, EMBED, 1.0f);
}

// round 10
// speedup vs baseline: 1.1643x; 1.1643x over previous
#include <cuda_runtime.h>
#include <cuda_fp16.h>
#include <math.h>
#include <stdint.h>

#define EMBED   1024
#define BATCH   2
#define SEQ     2048
#define NHEADS  8
#define HDIM    64
#define DVDIM   128
#define H2      16
#define LAMBDA_INIT 0.8f

// -------- scratch (static device arrays: allocation-free rule) --------
__device__ __half g_qi[BATCH*SEQ*EMBED];   // fp16 inputs
__device__ __half g_ki[BATCH*SEQ*EMBED];
__device__ __half g_vi[BATCH*SEQ*EMBED];
__device__ __half g_Wh[4*EMBED*EMBED];     // fp16 weights (q,k,v,o)
__device__ __half g_Qp[BATCH*SEQ*EMBED];   // fp16 projections
__device__ __half g_Kp[BATCH*SEQ*EMBED];
__device__ __half g_Vp[BATCH*SEQ*EMBED];
__device__ float  g_O [BATCH*H2*SEQ*DVDIM];
__device__ __half g_Xh[BATCH*SEQ*EMBED];
__device__ float  g_lambda;

// ---------------- helpers ----------------
__device__ __forceinline__ uint32_t smem_u32(const void* p) {
    uint32_t a;
    asm("{ .reg .u64 t; cvta.to.shared.u64 t, %1; cvt.u32.u64 %0, t; }"
        : "=r"(a) : "l"(p));
    return a;
}

__device__ __forceinline__ unsigned f2h2(float x, float y) {
    __half2 h = __floats2half2_rn(x, y);
    return *(unsigned*)&h;
}

__device__ __forceinline__ float ex2f(float x) {
    float y;
    asm("ex2.approx.f32 %0, %1;" : "=f"(y) : "f"(x));
    return y;
}

__device__ __forceinline__ unsigned e2pack(float x, float y) {
    unsigned h;
    float ex = ex2f(x), ey = ex2f(y);
    asm("cvt.rn.f16x2.f32 %0, %2, %1;" : "=r"(h) : "f"(ex), "f"(ey));
    return h;
}

__device__ __forceinline__ void mma16(float c[4], const unsigned a[4], const unsigned b[2]) {
    asm volatile(
        "mma.sync.aligned.m16n8k16.row.col.f32.f16.f16.f32 "
        "{%0,%1,%2,%3},{%4,%5,%6,%7},{%8,%9},{%0,%1,%2,%3};"
        : "+f"(c[0]), "+f"(c[1]), "+f"(c[2]), "+f"(c[3])
        : "r"(a[0]), "r"(a[1]), "r"(a[2]), "r"(a[3]), "r"(b[0]), "r"(b[1]));
}

__device__ __forceinline__ void ldsm4(uint32_t a, unsigned& r0, unsigned& r1,
                                      unsigned& r2, unsigned& r3) {
    asm volatile("ldmatrix.sync.aligned.m8n8.x4.shared.b16 {%0,%1,%2,%3}, [%4];"
                 : "=r"(r0), "=r"(r1), "=r"(r2), "=r"(r3) : "r"(a));
}

__device__ __forceinline__ void ldsm4t(uint32_t a, unsigned& r0, unsigned& r1,
                                       unsigned& r2, unsigned& r3) {
    asm volatile("ldmatrix.sync.aligned.m8n8.x4.trans.shared.b16 {%0,%1,%2,%3}, [%4];"
                 : "=r"(r0), "=r"(r1), "=r"(r2), "=r"(r3) : "r"(a));
}

#define CP16(dst, src) \
    asm volatile("cp.async.cg.shared.global [%0], [%1], 16;" :: "r"(dst), "l"(src))
#define CP_COMMIT() asm volatile("cp.async.commit_group;" ::: "memory")
#define CP_WAIT(n)  asm volatile("cp.async.wait_group %0;" :: "n"(n) : "memory")

// ======================================================================
// convert kernels: fp32 -> fp16 (vectorized, grid-stride)
// ======================================================================
__global__ void cvt3_kernel(const float* __restrict__ a0, const float* __restrict__ a1,
                            const float* __restrict__ a2,
                            __half* __restrict__ o0, __half* __restrict__ o1,
                            __half* __restrict__ o2, int n4)
{
    const float* src = blockIdx.y == 0 ? a0 : (blockIdx.y == 1 ? a1 : a2);
    __half* dst = blockIdx.y == 0 ? o0 : (blockIdx.y == 1 ? o1 : o2);
    for (int i = blockIdx.x * blockDim.x + threadIdx.x; i < n4;
         i += gridDim.x * blockDim.x) {
        float4 v = ((const float4*)src)[i];
        ((uint2*)dst)[i] = make_uint2(f2h2(v.x, v.y), f2h2(v.z, v.w));
    }
}

__global__ void cvt4_kernel(const float* __restrict__ a0, const float* __restrict__ a1,
                            const float* __restrict__ a2, const float* __restrict__ a3,
                            __half* __restrict__ out, int n4)
{
    const float* src = blockIdx.y == 0 ? a0 : (blockIdx.y == 1 ? a1
                       : (blockIdx.y == 2 ? a2 : a3));
    __half* dst = out + (size_t)blockIdx.y * EMBED * EMBED;
    for (int i = blockIdx.x * blockDim.x + threadIdx.x; i < n4;
         i += gridDim.x * blockDim.x) {
        float4 v = ((const float4*)src)[i];
        ((uint2*)dst)[i] = make_uint2(f2h2(v.x, v.y), f2h2(v.z, v.w));
    }
}

// ======================================================================
// fp16 GEMM core: C[M,N] = alpha * A[M,K] @ W[N,K]^T
// A, W fp16 in global; cp.async.cg double-buffered; HOUT: 1=fp16, 0=fp32.
// ======================================================================
#define GSTR 40
#define GBUF (128*GSTR)
template<int HOUT>
__device__ __forceinline__ void gemm_core(
    const __half* __restrict__ A, const __half* __restrict__ W,
    void* __restrict__ Cv, int N, int K, float alpha,
    __half (*As)[GBUF], __half (*Ws)[GBUF])
{
    const int tid = threadIdx.x, lane = tid & 31, warp = tid >> 5;
    const int wm = warp >> 2, wn = warp & 3;
    const int m0 = blockIdx.y << 7, n0 = blockIdx.x << 7;
    const int g = lane >> 2, q = lane & 3;
    const int lm = lane >> 3, lr = lane & 7;

    const int lrow = tid >> 1;
    const int lk   = (tid & 1) << 4;
    const __half* Ag = A + (size_t)(m0 + lrow) * K + lk;
    const __half* Wg = W + (size_t)(n0 + lrow) * K + lk;

    float acc[4][4][4] = {};

    const uint32_t aB = smem_u32(As), wB = smem_u32(Ws);
    const uint32_t sOff = (lrow * GSTR + lk) * 2;
    const int arow = (wm << 6) + ((lm & 1) << 3) + lr;
    const int acol = (lm >> 1) << 3;
    const int brow = (wn << 5) + ((lm >> 1) << 3) + lr;
    const int bcol = (lm & 1) << 3;

    // preload k-block 0 -> buf 0
    CP16(aB + sOff,      Ag);
    CP16(aB + sOff + 16, Ag + 8);
    CP16(wB + sOff,      Wg);
    CP16(wB + sOff + 16, Wg + 8);
    CP_COMMIT();

    const int NK = K >> 5;
    for (int kt = 0; kt < NK; ++kt) {
        if (kt + 1 < NK) {
            const int kc = (kt + 1) << 5;
            const uint32_t bo = ((kt + 1) & 1) * (GBUF * 2);
            CP16(aB + bo + sOff,      Ag + kc);
            CP16(aB + bo + sOff + 16, Ag + kc + 8);
            CP16(wB + bo + sOff,      Wg + kc);
            CP16(wB + bo + sOff + 16, Wg + kc + 8);
            CP_COMMIT();
            CP_WAIT(1);
        } else {
            CP_WAIT(0);
        }
        __syncthreads();

        const uint32_t aBb = aB + (kt & 1) * (GBUF * 2);
        const uint32_t wBb = wB + (kt & 1) * (GBUF * 2);
#pragma unroll
        for (int ks = 0; ks < 2; ++ks) {
            unsigned af[4][4], bf[4][2];
#pragma unroll
            for (int mi = 0; mi < 4; ++mi)
                ldsm4(aBb + ((arow + (mi << 4)) * GSTR + (ks << 4) + acol) * 2,
                      af[mi][0], af[mi][1], af[mi][2], af[mi][3]);
#pragma unroll
            for (int np = 0; np < 2; ++np) {
                unsigned r0, r1, r2, r3;
                ldsm4(wBb + ((brow + (np << 4)) * GSTR + (ks << 4) + bcol) * 2,
                      r0, r1, r2, r3);
                bf[2*np][0] = r0; bf[2*np][1] = r1;
                bf[2*np+1][0] = r2; bf[2*np+1][1] = r3;
            }
#pragma unroll
            for (int mi = 0; mi < 4; ++mi)
#pragma unroll
                for (int ni = 0; ni < 4; ++ni)
                    mma16(acc[mi][ni], af[mi], bf[ni]);
        }
        __syncthreads();
    }

#pragma unroll
    for (int mi = 0; mi < 4; ++mi)
#pragma unroll
        for (int ni = 0; ni < 4; ++ni) {
            const int r0 = m0 + (wm << 6) + (mi << 4) + g;
            const int cc = n0 + (wn << 5) + (ni << 3) + 2 * q;
            if (HOUT) {
                __half* C = (__half*)Cv;
                *(unsigned*)&C[(size_t)r0 * N + cc] =
                    f2h2(acc[mi][ni][0] * alpha, acc[mi][ni][1] * alpha);
                *(unsigned*)&C[(size_t)(r0 + 8) * N + cc] =
                    f2h2(acc[mi][ni][2] * alpha, acc[mi][ni][3] * alpha);
            } else {
                float* C = (float*)Cv;
                *(float2*)&C[(size_t)r0 * N + cc] =
                    make_float2(acc[mi][ni][0] * alpha, acc[mi][ni][1] * alpha);
                *(float2*)&C[(size_t)(r0 + 8) * N + cc] =
                    make_float2(acc[mi][ni][2] * alpha, acc[mi][ni][3] * alpha);
            }
        }
}

// batched QKV projection: blockIdx.z selects (input, weight, output, alpha)
__global__ void __launch_bounds__(256) gemm_qkv(
    const __half* __restrict__ qi, const __half* __restrict__ ki,
    const __half* __restrict__ vi, const __half* __restrict__ Wh,
    __half* __restrict__ Qp, __half* __restrict__ Kp, __half* __restrict__ Vp,
    float qscale)
{
    __shared__ __half As[2][GBUF];
    __shared__ __half Ws[2][GBUF];
    const int z = blockIdx.z;
    const __half* A = z == 0 ? qi : (z == 1 ? ki : vi);
    const __half* W = Wh + (size_t)z * EMBED * EMBED;
    __half* C = z == 0 ? Qp : (z == 1 ? Kp : Vp);
    const float alpha = z == 0 ? qscale : 1.0f;
    gemm_core<1>(A, W, C, EMBED, EMBED, alpha, As, Ws);
}

// output projection: fp16 A/W, fp32 out
__global__ void __launch_bounds__(256) gemm_o(
    const __half* __restrict__ Xh, const __half* __restrict__ Wh,
    float* __restrict__ out)
{
    __shared__ __half As[2][GBUF];
    __shared__ __half Ws[2][GBUF];
    gemm_core<0>(Xh, Wh + (size_t)3 * EMBED * EMBED, out, EMBED, EMBED, 1.0f, As, Ws);
}

// ======================================================================
// lambda_full
// ======================================================================
__global__ void lambda_kernel(const float* __restrict__ lq1, const float* __restrict__ lk1,
                              const float* __restrict__ lq2, const float* __restrict__ lk2)
{
    const int t = threadIdx.x;   // 64 threads
    float s1 = lq1[t] * lk1[t];
    float s2 = lq2[t] * lk2[t];
#pragma unroll
    for (int off = 16; off > 0; off >>= 1) {
        s1 += __shfl_xor_sync(0xffffffffu, s1, off);
        s2 += __shfl_xor_sync(0xffffffffu, s2, off);
    }
    __shared__ float w1[2], w2[2];
    if ((t & 31) == 0) { w1[t >> 5] = s1; w2[t >> 5] = s2; }
    __syncthreads();
    if (t == 0)
        g_lambda = expf(w1[0] + w1[1]) - expf(w2[0] + w2[1]) + LAMBDA_INIT;
}

// ======================================================================
// Flash attention (round-7 proven version): fp16 mma, no online softmax.
// CTA: 64 q-rows, 256 threads; 8 warps = 4 rowgroups x 2 col-halves.
// ======================================================================
#define KTB (64*72)
#define VTB (64*136)
__global__ void __launch_bounds__(256, 2) flash_fp16(
    const __half* __restrict__ Qp, const __half* __restrict__ Kp,
    const __half* __restrict__ Vp)
{
    extern __shared__ __half fsm[];
    __half* Qs = fsm;
    __half* Ks = fsm + KTB;
    __half* Vs = fsm + 3*KTB;

    const int tid = threadIdx.x, lane = tid & 31, wid = tid >> 5;
    const int g = lane >> 2, q = lane & 3;
    const int lm = lane >> 3, lr = lane & 7;
    const int rg = wid >> 1, ch = wid & 1;
    const int qt = blockIdx.x, bh = blockIdx.y;
    const int b = bh >> 4, h2 = bh & 15, hv = h2 >> 1;
    const int t0 = qt << 6;
    const int mrow = rg << 4;

    const __half* qg = Qp + (size_t)b*SEQ*EMBED + h2*HDIM;
    const __half* kg = Kp + (size_t)b*SEQ*EMBED + h2*HDIM;
    const __half* vg = Vp + (size_t)b*SEQ*EMBED + hv*DVDIM;

    const uint32_t qB = smem_u32(Qs), kB = smem_u32(Ks), vB = smem_u32(Vs);

#pragma unroll
    for (int it = 0; it < 2; ++it) {
        const int c = tid + (it << 8);
        const int row = c >> 3, off = (c & 7) << 3;
        *(uint4*)&Qs[row*72 + off] =
            *(const uint4*)&qg[(size_t)(t0 + row) * EMBED + off];
    }

    {
#pragma unroll
        for (int it = 0; it < 2; ++it) {
            const int c = tid + (it << 8);
            const int row = c >> 3, off = (c & 7) << 3;
            CP16(kB + (row*72 + off) * 2, kg + (size_t)row * EMBED + off);
        }
#pragma unroll
        for (int it = 0; it < 4; ++it) {
            const int c = tid + (it << 8);
            const int row = c >> 4, off = (c & 15) << 3;
            CP16(vB + (row*136 + off) * 2, vg + (size_t)row * EMBED + off);
        }
        CP_COMMIT();
    }
    __syncthreads();

    unsigned qa[4][4];
    {
        const int qrow = mrow + ((lm & 1) << 3) + lr;
        const int qcol = (lm >> 1) << 3;
#pragma unroll
        for (int ks = 0; ks < 4; ++ks)
            ldsm4(qB + (qrow*72 + (ks << 4) + qcol) * 2,
                  qa[ks][0], qa[ks][1], qa[ks][2], qa[ks][3]);
    }

    float o[8][4];
#pragma unroll
    for (int i = 0; i < 8; ++i)
#pragma unroll
        for (int r = 0; r < 4; ++r) o[i][r] = 0.f;
    float lacc[4] = {0.f, 0.f, 0.f, 0.f};
    const unsigned ones[2] = {0x3C003C00u, 0x3C003C00u};

    const int kfrow = ((lm >> 1) << 3) + lr;
    const int kcsel = (lm & 1) << 3;
    const int vfrow = ((lm & 1) << 3) + lr;
    const int vcsel = lm >> 1;

    const int NT = SEQ / 64;
    for (int ti = 0; ti < NT; ++ti) {
        const int buf = ti & 1;
        if (ti + 1 < NT) {
            const int s1r = (ti + 1) << 6;
            const uint32_t kD = kB + (buf ^ 1) * KTB * 2;
            const uint32_t vD = vB + (buf ^ 1) * VTB * 2;
#pragma unroll
            for (int it = 0; it < 2; ++it) {
                const int c = tid + (it << 8);
                const int row = c >> 3, off = (c & 7) << 3;
                CP16(kD + (row*72 + off) * 2, kg + (size_t)(s1r + row) * EMBED + off);
            }
#pragma unroll
            for (int it = 0; it < 4; ++it) {
                const int c = tid + (it << 8);
                const int row = c >> 4, off = (c & 15) << 3;
                CP16(vD + (row*136 + off) * 2, vg + (size_t)(s1r + row) * EMBED + off);
            }
            CP_COMMIT();
            CP_WAIT(1);
        } else {
            CP_WAIT(0);
        }
        __syncthreads();

        const uint32_t kBb = kB + buf * KTB * 2;
        const uint32_t vBb = vB + buf * VTB * 2;

        float s[8][4];
#pragma unroll
        for (int nt = 0; nt < 8; ++nt)
#pragma unroll
            for (int r = 0; r < 4; ++r) s[nt][r] = 0.f;
#pragma unroll
        for (int ks = 0; ks < 4; ++ks) {
            unsigned kb[8][2];
#pragma unroll
            for (int np = 0; np < 4; ++np) {
                unsigned r0, r1, r2, r3;
                ldsm4(kBb + (((np << 4) + kfrow)*72 + (ks << 4) + kcsel) * 2,
                      r0, r1, r2, r3);
                kb[2*np][0] = r0; kb[2*np][1] = r1;
                kb[2*np+1][0] = r2; kb[2*np+1][1] = r3;
            }
#pragma unroll
            for (int nt = 0; nt < 8; ++nt)
                mma16(s[nt], qa[ks], kb[nt]);
        }

        unsigned pa[4][4];
#pragma unroll
        for (int t = 0; t < 4; ++t) {
            pa[t][0] = e2pack(s[2*t][0],   s[2*t][1]);
            pa[t][1] = e2pack(s[2*t][2],   s[2*t][3]);
            pa[t][2] = e2pack(s[2*t+1][0], s[2*t+1][1]);
            pa[t][3] = e2pack(s[2*t+1][2], s[2*t+1][3]);
        }

#pragma unroll
        for (int t = 0; t < 4; ++t)
            mma16(lacc, pa[t], ones);

#pragma unroll
        for (int ks = 0; ks < 4; ++ks) {
#pragma unroll
            for (int cp = 0; cp < 4; ++cp) {
                unsigned r0, r1, r2, r3;
                const int colt = (ch << 3) + (cp << 1);
                ldsm4t(vBb + (((ks << 4) + vfrow)*136 + (colt + vcsel)*8) * 2,
                       r0, r1, r2, r3);
                unsigned vb0[2] = {r0, r1}, vb1[2] = {r2, r3};
                mma16(o[2*cp],   pa[ks], vb0);
                mma16(o[2*cp+1], pa[ks], vb1);
            }
        }
        __syncthreads();
    }

    const float inv0 = 1.f / lacc[0], inv1 = 1.f / lacc[2];
    float* ob = g_O + ((size_t)bh * SEQ + t0) * DVDIM + (ch << 6);
#pragma unroll
    for (int ct = 0; ct < 8; ++ct) {
        const int col = (ct << 3) + 2 * q;
        *(float2*)&ob[(size_t)(mrow + g)     * DVDIM + col] =
            make_float2(o[ct][0] * inv0, o[ct][1] * inv0);
        *(float2*)&ob[(size_t)(mrow + 8 + g) * DVDIM + col] =
            make_float2(o[ct][2] * inv1, o[ct][3] * inv1);
    }
}

// ======================================================================
// Combine: y = O[2h] - lambda*O[2h+1]; RMSNorm over 128; write fp16 X
// ======================================================================
__global__ void __launch_bounds__(128) combine_kernel(
    const float* __restrict__ O, __half* __restrict__ Xh)
{
    const int t = blockIdx.x, h = blockIdx.y, b = blockIdx.z;
    const int c = threadIdx.x;
    const float lam = g_lambda;
    const size_t i0 = (((size_t)b*H2 + 2*h  )*SEQ + t)*DVDIM + c;
    const size_t i1 = (((size_t)b*H2 + 2*h+1)*SEQ + t)*DVDIM + c;
    float y = O[i0] - lam * O[i1];

    float v = y * y;
#pragma unroll
    for (int off = 16; off > 0; off >>= 1)
        v += __shfl_xor_sync(0xffffffffu, v, off);
    __shared__ float ws[4];
    if ((c & 31) == 0) ws[c >> 5] = v;
    __syncthreads();
    float tot = ws[0] + ws[1] + ws[2] + ws[3];
    float r = rsqrtf(tot * (1.f/128.f) + 1e-5f);
    Xh[((size_t)b*SEQ + t)*EMBED + h*DVDIM + c] =
        __float2half(y * r * (1.f - LAMBDA_INIT));
}

// ======================================================================
extern "C" void kernel_launch(void* const* d_in, const int* in_sizes, int n_in,
                              void* d_out, int out_size)
{
    const float* q   = (const float*)d_in[0];
    const float* k   = (const float*)d_in[1];
    const float* v   = (const float*)d_in[2];
    const float* Wq  = (const float*)d_in[3];
    const float* Wk  = (const float*)d_in[4];
    const float* Wv  = (const float*)d_in[5];
    const float* Wo  = (const float*)d_in[6];
    const float* lq1 = (const float*)d_in[7];
    const float* lk1 = (const float*)d_in[8];
    const float* lq2 = (const float*)d_in[9];
    const float* lk2 = (const float*)d_in[10];
    float* out = (float*)d_out;

    __half *qi, *ki, *vi, *Wh, *Qp, *Kp, *Vp, *Xh;
    float *O;
    cudaGetSymbolAddress((void**)&qi, g_qi);
    cudaGetSymbolAddress((void**)&ki, g_ki);
    cudaGetSymbolAddress((void**)&vi, g_vi);
    cudaGetSymbolAddress((void**)&Wh, g_Wh);
    cudaGetSymbolAddress((void**)&Qp, g_Qp);
    cudaGetSymbolAddress((void**)&Kp, g_Kp);
    cudaGetSymbolAddress((void**)&Vp, g_Vp);
    cudaGetSymbolAddress((void**)&O,  g_O);
    cudaGetSymbolAddress((void**)&Xh, g_Xh);

    const int SMEM_FLASH = (KTB + 2*KTB + 2*VTB) * (int)sizeof(__half); // 62464
    cudaFuncSetAttribute(flash_fp16,
                         cudaFuncAttributeMaxDynamicSharedMemorySize, SMEM_FLASH);

    const int M = BATCH * SEQ;          // 4096
    const float qscale = 0.125f * 1.4426950408889634f;  // d^-0.5 * log2(e)

    const int N4_IN = BATCH*SEQ*EMBED/4;   // 1048576
    const int N4_W  = EMBED*EMBED/4;       // 262144

    lambda_kernel<<<1, 64>>>(lq1, lk1, lq2, lk2);
    cvt3_kernel<<<dim3(512, 3), 256>>>(q, k, v, qi, ki, vi, N4_IN);
    cvt4_kernel<<<dim3(256, 4), 256>>>(Wq, Wk, Wv, Wo, Wh, N4_W);
    gemm_qkv<<<dim3(EMBED/128, M/128, 3), 256>>>(qi, ki, vi, Wh, Qp, Kp, Vp, qscale);
    flash_fp16<<<dim3(SEQ/64, BATCH*H2), 256, SMEM_FLASH>>>(Qp, Kp, Vp);
    combine_kernel<<<dim3(SEQ, NHEADS, BATCH), 128>>>(O, Xh);
    gemm_o<<<dim3(EMBED/128, M/128), 256>>>(Xh, Wh, out);
}

// round 11
// speedup vs baseline: 1.2979x; 1.1147x over previous
#include <cuda_runtime.h>
#include <cuda_fp16.h>
#include <math.h>
#include <stdint.h>

#define EMBED   1024
#define BATCH   2
#define SEQ     2048
#define NHEADS  8
#define HDIM    64
#define DVDIM   128
#define H2      16
#define LAMBDA_INIT 0.8f

// -------- scratch (static device arrays: allocation-free rule) --------
__device__ __half g_qi[BATCH*SEQ*EMBED];
__device__ __half g_ki[BATCH*SEQ*EMBED];
__device__ __half g_vi[BATCH*SEQ*EMBED];
__device__ __half g_Wh[4*EMBED*EMBED];
__device__ __half g_Qp[BATCH*SEQ*EMBED];
__device__ __half g_Kp[BATCH*SEQ*EMBED];
__device__ __half g_Vp[BATCH*SEQ*EMBED];
__device__ float  g_O [BATCH*H2*SEQ*DVDIM];
__device__ __half g_Xh[BATCH*SEQ*EMBED];
__device__ float  g_lambda;

// ---------------- helpers ----------------
__device__ __forceinline__ uint32_t smem_u32(const void* p) {
    uint32_t a;
    asm("{ .reg .u64 t; cvta.to.shared.u64 t, %1; cvt.u32.u64 %0, t; }"
        : "=r"(a) : "l"(p));
    return a;
}

__device__ __forceinline__ unsigned f2h2(float x, float y) {
    __half2 h = __floats2half2_rn(x, y);
    return *(unsigned*)&h;
}

__device__ __forceinline__ float ex2f(float x) {
    float y;
    asm("ex2.approx.f32 %0, %1;" : "=f"(y) : "f"(x));
    return y;
}

__device__ __forceinline__ unsigned e2pack(float x, float y) {
    unsigned h;
    float ex = ex2f(x), ey = ex2f(y);
    asm("cvt.rn.f16x2.f32 %0, %2, %1;" : "=r"(h) : "f"(ex), "f"(ey));
    return h;
}

__device__ __forceinline__ void mma16(float c[4], const unsigned a[4], const unsigned b[2]) {
    asm volatile(
        "mma.sync.aligned.m16n8k16.row.col.f32.f16.f16.f32 "
        "{%0,%1,%2,%3},{%4,%5,%6,%7},{%8,%9},{%0,%1,%2,%3};"
        : "+f"(c[0]), "+f"(c[1]), "+f"(c[2]), "+f"(c[3])
        : "r"(a[0]), "r"(a[1]), "r"(a[2]), "r"(a[3]), "r"(b[0]), "r"(b[1]));
}

__device__ __forceinline__ void ldsm4(uint32_t a, unsigned& r0, unsigned& r1,
                                      unsigned& r2, unsigned& r3) {
    asm volatile("ldmatrix.sync.aligned.m8n8.x4.shared.b16 {%0,%1,%2,%3}, [%4];"
                 : "=r"(r0), "=r"(r1), "=r"(r2), "=r"(r3) : "r"(a));
}

__device__ __forceinline__ void ldsm4t(uint32_t a, unsigned& r0, unsigned& r1,
                                       unsigned& r2, unsigned& r3) {
    asm volatile("ldmatrix.sync.aligned.m8n8.x4.trans.shared.b16 {%0,%1,%2,%3}, [%4];"
                 : "=r"(r0), "=r"(r1), "=r"(r2), "=r"(r3) : "r"(a));
}

#define CP16(dst, src) \
    asm volatile("cp.async.cg.shared.global [%0], [%1], 16;" :: "r"(dst), "l"(src))
#define CP_COMMIT() asm volatile("cp.async.commit_group;" ::: "memory")
#define CP_WAIT(n)  asm volatile("cp.async.wait_group %0;" :: "n"(n) : "memory")

// ======================================================================
// convert kernels: fp32 -> fp16
// ======================================================================
__global__ void cvt3_kernel(const float* __restrict__ a0, const float* __restrict__ a1,
                            const float* __restrict__ a2,
                            __half* __restrict__ o0, __half* __restrict__ o1,
                            __half* __restrict__ o2, int n4)
{
    const float* src = blockIdx.y == 0 ? a0 : (blockIdx.y == 1 ? a1 : a2);
    __half* dst = blockIdx.y == 0 ? o0 : (blockIdx.y == 1 ? o1 : o2);
    for (int i = blockIdx.x * blockDim.x + threadIdx.x; i < n4;
         i += gridDim.x * blockDim.x) {
        float4 v = ((const float4*)src)[i];
        ((uint2*)dst)[i] = make_uint2(f2h2(v.x, v.y), f2h2(v.z, v.w));
    }
}

__global__ void cvt4_kernel(const float* __restrict__ a0, const float* __restrict__ a1,
                            const float* __restrict__ a2, const float* __restrict__ a3,
                            __half* __restrict__ out, int n4)
{
    const float* src = blockIdx.y == 0 ? a0 : (blockIdx.y == 1 ? a1
                       : (blockIdx.y == 2 ? a2 : a3));
    __half* dst = out + (size_t)blockIdx.y * EMBED * EMBED;
    for (int i = blockIdx.x * blockDim.x + threadIdx.x; i < n4;
         i += gridDim.x * blockDim.x) {
        float4 v = ((const float4*)src)[i];
        ((uint2*)dst)[i] = make_uint2(f2h2(v.x, v.y), f2h2(v.z, v.w));
    }
}

// ======================================================================
// fp16 GEMM core: 3-stage cp.async pipeline, ONE barrier per k-block.
// C[M,N] = alpha * A[M,K] @ W[N,K]^T ; HOUT: 1=fp16 out, 0=fp32 out.
// dynamic smem: 3 stages x (A 10240B + W 10240B) = 61440 B
// ======================================================================
#define GSTR 40
#define GBUF (128*GSTR)
#define GSTG 3
template<int HOUT>
__device__ __forceinline__ void gemm_core(
    const __half* __restrict__ A, const __half* __restrict__ W,
    void* __restrict__ Cv, int N, int K, float alpha, __half* sm)
{
    const int tid = threadIdx.x, lane = tid & 31, warp = tid >> 5;
    const int wm = warp >> 2, wn = warp & 3;
    const int m0 = blockIdx.y << 7, n0 = blockIdx.x << 7;
    const int g = lane >> 2, q = lane & 3;
    const int lm = lane >> 3, lr = lane & 7;

    const int lrow = tid >> 1;
    const int lk   = (tid & 1) << 4;
    const __half* Ag = A + (size_t)(m0 + lrow) * K + lk;
    const __half* Wg = W + (size_t)(n0 + lrow) * K + lk;

    float acc[4][4][4] = {};

    const uint32_t aB = smem_u32(sm);
    const uint32_t wB = aB + GSTG * (GBUF * 2);
    const uint32_t sOff = (lrow * GSTR + lk) * 2;
    const int arow = (wm << 6) + ((lm & 1) << 3) + lr;
    const int acol = (lm >> 1) << 3;
    const int brow = (wn << 5) + ((lm >> 1) << 3) + lr;
    const int bcol = (lm & 1) << 3;

    // preload stages 0..GSTG-2
#pragma unroll
    for (int s = 0; s < GSTG - 1; ++s) {
        const int kc = s << 5;
        CP16(aB + s*(GBUF*2) + sOff,      Ag + kc);
        CP16(aB + s*(GBUF*2) + sOff + 16, Ag + kc + 8);
        CP16(wB + s*(GBUF*2) + sOff,      Wg + kc);
        CP16(wB + s*(GBUF*2) + sOff + 16, Wg + kc + 8);
        CP_COMMIT();
    }

    const int NK = K >> 5;
    int sb = 0, sd = GSTG - 1;
    for (int kt = 0; kt < NK; ++kt) {
        if (kt + 1 < NK) { CP_WAIT(GSTG - 2); } else { CP_WAIT(0); }
        __syncthreads();

        const uint32_t aBb = aB + sb * (GBUF * 2);
        const uint32_t wBb = wB + sb * (GBUF * 2);
#pragma unroll
        for (int ks = 0; ks < 2; ++ks) {
            unsigned af[4][4], bf[4][2];
#pragma unroll
            for (int mi = 0; mi < 4; ++mi)
                ldsm4(aBb + ((arow + (mi << 4)) * GSTR + (ks << 4) + acol) * 2,
                      af[mi][0], af[mi][1], af[mi][2], af[mi][3]);
#pragma unroll
            for (int np = 0; np < 2; ++np) {
                unsigned r0, r1, r2, r3;
                ldsm4(wBb + ((brow + (np << 4)) * GSTR + (ks << 4) + bcol) * 2,
                      r0, r1, r2, r3);
                bf[2*np][0] = r0; bf[2*np][1] = r1;
                bf[2*np+1][0] = r2; bf[2*np+1][1] = r3;
            }
#pragma unroll
            for (int mi = 0; mi < 4; ++mi)
#pragma unroll
                for (int ni = 0; ni < 4; ++ni)
                    mma16(acc[mi][ni], af[mi], bf[ni]);
        }

        if (kt + GSTG - 1 < NK) {
            const int kc = (kt + GSTG - 1) << 5;
            CP16(aB + sd*(GBUF*2) + sOff,      Ag + kc);
            CP16(aB + sd*(GBUF*2) + sOff + 16, Ag + kc + 8);
            CP16(wB + sd*(GBUF*2) + sOff,      Wg + kc);
            CP16(wB + sd*(GBUF*2) + sOff + 16, Wg + kc + 8);
            CP_COMMIT();
        }
        if (++sb == GSTG) sb = 0;
        if (++sd == GSTG) sd = 0;
    }

#pragma unroll
    for (int mi = 0; mi < 4; ++mi)
#pragma unroll
        for (int ni = 0; ni < 4; ++ni) {
            const int r0 = m0 + (wm << 6) + (mi << 4) + g;
            const int cc = n0 + (wn << 5) + (ni << 3) + 2 * q;
            if (HOUT) {
                __half* C = (__half*)Cv;
                *(unsigned*)&C[(size_t)r0 * N + cc] =
                    f2h2(acc[mi][ni][0] * alpha, acc[mi][ni][1] * alpha);
                *(unsigned*)&C[(size_t)(r0 + 8) * N + cc] =
                    f2h2(acc[mi][ni][2] * alpha, acc[mi][ni][3] * alpha);
            } else {
                float* C = (float*)Cv;
                *(float2*)&C[(size_t)r0 * N + cc] =
                    make_float2(acc[mi][ni][0] * alpha, acc[mi][ni][1] * alpha);
                *(float2*)&C[(size_t)(r0 + 8) * N + cc] =
                    make_float2(acc[mi][ni][2] * alpha, acc[mi][ni][3] * alpha);
            }
        }
}

__global__ void __launch_bounds__(256) gemm_qkv(
    const __half* __restrict__ qi, const __half* __restrict__ ki,
    const __half* __restrict__ vi, const __half* __restrict__ Wh,
    __half* __restrict__ Qp, __half* __restrict__ Kp, __half* __restrict__ Vp,
    float qscale)
{
    extern __shared__ __half gsm[];
    const int z = blockIdx.z;
    const __half* A = z == 0 ? qi : (z == 1 ? ki : vi);
    const __half* W = Wh + (size_t)z * EMBED * EMBED;
    __half* C = z == 0 ? Qp : (z == 1 ? Kp : Vp);
    const float alpha = z == 0 ? qscale : 1.0f;
    gemm_core<1>(A, W, C, EMBED, EMBED, alpha, gsm);
}

__global__ void __launch_bounds__(256) gemm_o(
    const __half* __restrict__ Xh, const __half* __restrict__ Wh,
    float* __restrict__ out)
{
    extern __shared__ __half gsm[];
    gemm_core<0>(Xh, Wh + (size_t)3 * EMBED * EMBED, out, EMBED, EMBED, 1.0f, gsm);
}

// ======================================================================
// lambda_full
// ======================================================================
__global__ void lambda_kernel(const float* __restrict__ lq1, const float* __restrict__ lk1,
                              const float* __restrict__ lq2, const float* __restrict__ lk2)
{
    const int t = threadIdx.x;
    float s1 = lq1[t] * lk1[t];
    float s2 = lq2[t] * lk2[t];
#pragma unroll
    for (int off = 16; off > 0; off >>= 1) {
        s1 += __shfl_xor_sync(0xffffffffu, s1, off);
        s2 += __shfl_xor_sync(0xffffffffu, s2, off);
    }
    __shared__ float w1[2], w2[2];
    if ((t & 31) == 0) { w1[t >> 5] = s1; w2[t >> 5] = s2; }
    __syncthreads();
    if (t == 0)
        g_lambda = expf(w1[0] + w1[1]) - expf(w2[0] + w2[1]) + LAMBDA_INIT;
}

// ======================================================================
// Flash attention: fp16 mma, no online softmax, 3-stage cp.async K/V,
// ONE barrier per key tile. CTA: 64 q-rows, 256 threads, occ 2.
// smem: Q 9216 + 3x(K 9216) + 3x(V 17408) = 89088 B
// ======================================================================
#define KTB (64*72)
#define VTB (64*136)
#define FSTG 3
__global__ void __launch_bounds__(256, 2) flash_fp16(
    const __half* __restrict__ Qp, const __half* __restrict__ Kp,
    const __half* __restrict__ Vp)
{
    extern __shared__ __half fsm[];
    __half* Qs = fsm;                       // KTB halves
    __half* Ks = fsm + KTB;                 // 3 stages
    __half* Vs = fsm + (1 + FSTG) * KTB;    // 3 stages

    const int tid = threadIdx.x, lane = tid & 31, wid = tid >> 5;
    const int g = lane >> 2, q = lane & 3;
    const int lm = lane >> 3, lr = lane & 7;
    const int rg = wid >> 1, ch = wid & 1;
    const int qt = blockIdx.x, bh = blockIdx.y;
    const int b = bh >> 4, h2 = bh & 15, hv = h2 >> 1;
    const int t0 = qt << 6;
    const int mrow = rg << 4;

    const __half* qg = Qp + (size_t)b*SEQ*EMBED + h2*HDIM;
    const __half* kg = Kp + (size_t)b*SEQ*EMBED + h2*HDIM;
    const __half* vg = Vp + (size_t)b*SEQ*EMBED + hv*DVDIM;

    const uint32_t qB = smem_u32(Qs), kB = smem_u32(Ks), vB = smem_u32(Vs);

    // Q tile -> smem (regular stores)
#pragma unroll
    for (int it = 0; it < 2; ++it) {
        const int c = tid + (it << 8);
        const int row = c >> 3, off = (c & 7) << 3;
        *(uint4*)&Qs[row*72 + off] =
            *(const uint4*)&qg[(size_t)(t0 + row) * EMBED + off];
    }

    // preload K/V tiles 0..1
#pragma unroll
    for (int pt = 0; pt < FSTG - 1; ++pt) {
        const int rb = pt << 6;
        const uint32_t kD = kB + pt * (KTB * 2);
        const uint32_t vD = vB + pt * (VTB * 2);
#pragma unroll
        for (int it = 0; it < 2; ++it) {
            const int c = tid + (it << 8);
            const int row = c >> 3, off = (c & 7) << 3;
            CP16(kD + (row*72 + off) * 2, kg + (size_t)(rb + row) * EMBED + off);
        }
#pragma unroll
        for (int it = 0; it < 4; ++it) {
            const int c = tid + (it << 8);
            const int row = c >> 4, off = (c & 15) << 3;
            CP16(vD + (row*136 + off) * 2, vg + (size_t)(rb + row) * EMBED + off);
        }
        CP_COMMIT();
    }
    __syncthreads();   // Qs visible

    unsigned qa[4][4];
    {
        const int qrow = mrow + ((lm & 1) << 3) + lr;
        const int qcol = (lm >> 1) << 3;
#pragma unroll
        for (int ks = 0; ks < 4; ++ks)
            ldsm4(qB + (qrow*72 + (ks << 4) + qcol) * 2,
                  qa[ks][0], qa[ks][1], qa[ks][2], qa[ks][3]);
    }

    float o[8][4];
#pragma unroll
    for (int i = 0; i < 8; ++i)
#pragma unroll
        for (int r = 0; r < 4; ++r) o[i][r] = 0.f;
    float lacc[4] = {0.f, 0.f, 0.f, 0.f};
    const unsigned ones[2] = {0x3C003C00u, 0x3C003C00u};

    const int kfrow = ((lm >> 1) << 3) + lr;
    const int kcsel = (lm & 1) << 3;
    const int vfrow = ((lm & 1) << 3) + lr;
    const int vcsel = lm >> 1;

    const int NT = SEQ / 64;
    int sb = 0, sd = FSTG - 1;
    for (int ti = 0; ti < NT; ++ti) {
        if (ti + 1 < NT) { CP_WAIT(FSTG - 2); } else { CP_WAIT(0); }
        __syncthreads();

        const uint32_t kBb = kB + sb * (KTB * 2);
        const uint32_t vBb = vB + sb * (VTB * 2);

        // S = Q @ K^T
        float s[8][4];
#pragma unroll
        for (int nt = 0; nt < 8; ++nt)
#pragma unroll
            for (int r = 0; r < 4; ++r) s[nt][r] = 0.f;
#pragma unroll
        for (int ks = 0; ks < 4; ++ks) {
            unsigned kb[8][2];
#pragma unroll
            for (int np = 0; np < 4; ++np) {
                unsigned r0, r1, r2, r3;
                ldsm4(kBb + (((np << 4) + kfrow)*72 + (ks << 4) + kcsel) * 2,
                      r0, r1, r2, r3);
                kb[2*np][0] = r0; kb[2*np][1] = r1;
                kb[2*np+1][0] = r2; kb[2*np+1][1] = r3;
            }
#pragma unroll
            for (int nt = 0; nt < 8; ++nt)
                mma16(s[nt], qa[ks], kb[nt]);
        }

        // P = exp2(S)
        unsigned pa[4][4];
#pragma unroll
        for (int t = 0; t < 4; ++t) {
            pa[t][0] = e2pack(s[2*t][0],   s[2*t][1]);
            pa[t][1] = e2pack(s[2*t][2],   s[2*t][3]);
            pa[t][2] = e2pack(s[2*t+1][0], s[2*t+1][1]);
            pa[t][3] = e2pack(s[2*t+1][2], s[2*t+1][3]);
        }

        // l += P @ ones
#pragma unroll
        for (int t = 0; t < 4; ++t)
            mma16(lacc, pa[t], ones);

        // O += P @ V
#pragma unroll
        for (int ks = 0; ks < 4; ++ks) {
#pragma unroll
            for (int cp = 0; cp < 4; ++cp) {
                unsigned r0, r1, r2, r3;
                const int colt = (ch << 3) + (cp << 1);
                ldsm4t(vBb + (((ks << 4) + vfrow)*136 + (colt + vcsel)*8) * 2,
                       r0, r1, r2, r3);
                unsigned vb0[2] = {r0, r1}, vb1[2] = {r2, r3};
                mma16(o[2*cp],   pa[ks], vb0);
                mma16(o[2*cp+1], pa[ks], vb1);
            }
        }

        // issue tile ti+2 into stage sd
        if (ti + FSTG - 1 < NT) {
            const int rb = (ti + FSTG - 1) << 6;
            const uint32_t kD = kB + sd * (KTB * 2);
            const uint32_t vD = vB + sd * (VTB * 2);
#pragma unroll
            for (int it = 0; it < 2; ++it) {
                const int c = tid + (it << 8);
                const int row = c >> 3, off = (c & 7) << 3;
                CP16(kD + (row*72 + off) * 2, kg + (size_t)(rb + row) * EMBED + off);
            }
#pragma unroll
            for (int it = 0; it < 4; ++it) {
                const int c = tid + (it << 8);
                const int row = c >> 4, off = (c & 15) << 3;
                CP16(vD + (row*136 + off) * 2, vg + (size_t)(rb + row) * EMBED + off);
            }
            CP_COMMIT();
        }
        if (++sb == FSTG) sb = 0;
        if (++sd == FSTG) sd = 0;
    }

    const float inv0 = 1.f / lacc[0], inv1 = 1.f / lacc[2];
    float* ob = g_O + ((size_t)bh * SEQ + t0) * DVDIM + (ch << 6);
#pragma unroll
    for (int ct = 0; ct < 8; ++ct) {
        const int col = (ct << 3) + 2 * q;
        *(float2*)&ob[(size_t)(mrow + g)     * DVDIM + col] =
            make_float2(o[ct][0] * inv0, o[ct][1] * inv0);
        *(float2*)&ob[(size_t)(mrow + 8 + g) * DVDIM + col] =
            make_float2(o[ct][2] * inv1, o[ct][3] * inv1);
    }
}

// ======================================================================
// Combine: y = O[2h] - lambda*O[2h+1]; RMSNorm over 128; write fp16 X
// ======================================================================
__global__ void __launch_bounds__(128) combine_kernel(
    const float* __restrict__ O, __half* __restrict__ Xh)
{
    const int t = blockIdx.x, h = blockIdx.y, b = blockIdx.z;
    const int c = threadIdx.x;
    const float lam = g_lambda;
    const size_t i0 = (((size_t)b*H2 + 2*h  )*SEQ + t)*DVDIM + c;
    const size_t i1 = (((size_t)b*H2 + 2*h+1)*SEQ + t)*DVDIM + c;
    float y = O[i0] - lam * O[i1];

    float v = y * y;
#pragma unroll
    for (int off = 16; off > 0; off >>= 1)
        v += __shfl_xor_sync(0xffffffffu, v, off);
    __shared__ float ws[4];
    if ((c & 31) == 0) ws[c >> 5] = v;
    __syncthreads();
    float tot = ws[0] + ws[1] + ws[2] + ws[3];
    float r = rsqrtf(tot * (1.f/128.f) + 1e-5f);
    Xh[((size_t)b*SEQ + t)*EMBED + h*DVDIM + c] =
        __float2half(y * r * (1.f - LAMBDA_INIT));
}

// ======================================================================
extern "C" void kernel_launch(void* const* d_in, const int* in_sizes, int n_in,
                              void* d_out, int out_size)
{
    const float* q   = (const float*)d_in[0];
    const float* k   = (const float*)d_in[1];
    const float* v   = (const float*)d_in[2];
    const float* Wq  = (const float*)d_in[3];
    const float* Wk  = (const float*)d_in[4];
    const float* Wv  = (const float*)d_in[5];
    const float* Wo  = (const float*)d_in[6];
    const float* lq1 = (const float*)d_in[7];
    const float* lk1 = (const float*)d_in[8];
    const float* lq2 = (const float*)d_in[9];
    const float* lk2 = (const float*)d_in[10];
    float* out = (float*)d_out;

    __half *qi, *ki, *vi, *Wh, *Qp, *Kp, *Vp, *Xh;
    float *O;
    cudaGetSymbolAddress((void**)&qi, g_qi);
    cudaGetSymbolAddress((void**)&ki, g_ki);
    cudaGetSymbolAddress((void**)&vi, g_vi);
    cudaGetSymbolAddress((void**)&Wh, g_Wh);
    cudaGetSymbolAddress((void**)&Qp, g_Qp);
    cudaGetSymbolAddress((void**)&Kp, g_Kp);
    cudaGetSymbolAddress((void**)&Vp, g_Vp);
    cudaGetSymbolAddress((void**)&O,  g_O);
    cudaGetSymbolAddress((void**)&Xh, g_Xh);

    const int SMEM_GEMM  = 2 * GSTG * GBUF * (int)sizeof(__half);              // 61440
    const int SMEM_FLASH = ((1 + FSTG) * KTB + FSTG * VTB) * (int)sizeof(__half); // 89088
    cudaFuncSetAttribute(gemm_qkv,
                         cudaFuncAttributeMaxDynamicSharedMemorySize, SMEM_GEMM);
    cudaFuncSetAttribute(gemm_o,
                         cudaFuncAttributeMaxDynamicSharedMemorySize, SMEM_GEMM);
    cudaFuncSetAttribute(flash_fp16,
                         cudaFuncAttributeMaxDynamicSharedMemorySize, SMEM_FLASH);

    const int M = BATCH * SEQ;
    const float qscale = 0.125f * 1.4426950408889634f;

    const int N4_IN = BATCH*SEQ*EMBED/4;
    const int N4_W  = EMBED*EMBED/4;

    lambda_kernel<<<1, 64>>>(lq1, lk1, lq2, lk2);
    cvt3_kernel<<<dim3(512, 3), 256>>>(q, k, v, qi, ki, vi, N4_IN);
    cvt4_kernel<<<dim3(256, 4), 256>>>(Wq, Wk, Wv, Wo, Wh, N4_W);
    gemm_qkv<<<dim3(EMBED/128, M/128, 3), 256, SMEM_GEMM>>>(qi, ki, vi, Wh, Qp, Kp, Vp, qscale);
    flash_fp16<<<dim3(SEQ/64, BATCH*H2), 256, SMEM_FLASH>>>(Qp, Kp, Vp);
    combine_kernel<<<dim3(SEQ, NHEADS, BATCH), 128>>>(O, Xh);
    gemm_o<<<dim3(EMBED/128, M/128), 256, SMEM_GEMM>>>(Xh, Wh, out);
}